// round 14
// baseline (speedup 1.0000x reference)
#include <cuda_runtime.h>
#include <cuda_fp16.h>
#include <cstdint>

// Scratch (allocation-free rule: device globals)
__device__ __align__(16) __half g_kh[4194304];
__device__ __align__(16) __half g_vh[4194304];
__device__ __align__(16) __half g_xh[4194304];   // attention out (half), [B*N, D]
__device__ __align__(16) __half g_hh[4194304];   // MLP hidden (half), [B*N, D]
__device__ __align__(16) __half g_w1h[1048576];  // W1^T [out][in] half
__device__ __align__(16) __half g_w2h[1048576];  // W2^T [out][in] half

__device__ __forceinline__ uint32_t h2u(float a, float b) {
    __half2 h = __floats2half2_rn(a, b);
    return *reinterpret_cast<uint32_t*>(&h);
}
__device__ __forceinline__ uint32_t smem_u32(const void* p) {
    uint32_t a;
    asm("{ .reg .u64 t; cvta.to.shared.u64 t, %1; cvt.u32.u64 %0, t; }" : "=r"(a) : "l"(p));
    return a;
}
__device__ __forceinline__ void cpa16(uint32_t dst, const void* src) {
    asm volatile("cp.async.cg.shared.global [%0], [%1], 16;" :: "r"(dst), "l"(src));
}
#define CP_COMMIT() asm volatile("cp.async.commit_group;" ::: "memory")
#define CP_WAIT(n)  asm volatile("cp.async.wait_group %0;" :: "n"(n) : "memory")

__device__ __forceinline__ void ldsm4(uint32_t* r, uint32_t a) {
    asm volatile("ldmatrix.sync.aligned.m8n8.x4.shared.b16 {%0,%1,%2,%3}, [%4];"
        : "=r"(r[0]), "=r"(r[1]), "=r"(r[2]), "=r"(r[3]) : "r"(a));
}
__device__ __forceinline__ void ldsm4t(uint32_t* r, uint32_t a) {
    asm volatile("ldmatrix.sync.aligned.m8n8.x4.trans.shared.b16 {%0,%1,%2,%3}, [%4];"
        : "=r"(r[0]), "=r"(r[1]), "=r"(r[2]), "=r"(r[3]) : "r"(a));
}

// fp32-accumulate MMA
__device__ __forceinline__ void mma16(float* c, const uint32_t* a, const uint32_t* b) {
    asm volatile("mma.sync.aligned.m16n8k16.row.col.f32.f16.f16.f32 "
        "{%0,%1,%2,%3}, {%4,%5,%6,%7}, {%8,%9}, {%0,%1,%2,%3};"
        : "+f"(c[0]), "+f"(c[1]), "+f"(c[2]), "+f"(c[3])
        : "r"(a[0]), "r"(a[1]), "r"(a[2]), "r"(a[3]), "r"(b[0]), "r"(b[1]));
}
// fp16-accumulate MMA
__device__ __forceinline__ void mma16h(uint32_t* c, const uint32_t* a, const uint32_t* b) {
    asm volatile("mma.sync.aligned.m16n8k16.row.col.f16.f16.f16.f16 "
        "{%0,%1}, {%2,%3,%4,%5}, {%6,%7}, {%0,%1};"
        : "+r"(c[0]), "+r"(c[1])
        : "r"(a[0]), "r"(a[1]), "r"(a[2]), "r"(a[3]), "r"(b[0]), "r"(b[1]));
}
__device__ __forceinline__ uint32_t ex2h2(uint32_t x) {
    uint32_t r; asm("ex2.approx.f16x2 %0, %1;" : "=r"(r) : "r"(x)); return r;
}

// ---------------------------------------------------------------------------
// Merged prep: k/v cvt [0,8192), W1/W2 transpose+cvt [8192,10240).
// q and pe are consumed fp32 directly by the attention kernel (no prep).
// ---------------------------------------------------------------------------
__global__ __launch_bounds__(256)
void prep_all(const float4* __restrict__ k, const float4* __restrict__ v,
              const float* __restrict__ w1, const float* __restrict__ w2,
              uint2* __restrict__ ko, uint2* __restrict__ vo,
              __half* __restrict__ w1t, __half* __restrict__ w2t)
{
    __shared__ float tile[32][33];
    const int bid = blockIdx.x;
    if (bid < 8192) {
        const int sec = bid >> 12;
        const int i = (bid & 4095) * 256 + threadIdx.x;
        const float4* s = sec == 0 ? k : v;
        uint2* d = sec == 0 ? ko : vo;
        float4 t = s[i];
        d[i] = make_uint2(h2u(t.x, t.y), h2u(t.z, t.w));
    } else {
        int t = bid - 8192;
        const float* src = t < 1024 ? w1 : w2;
        __half* dst = t < 1024 ? w1t : w2t;
        t &= 1023;
        const int bx = t & 31, by = t >> 5;
        const int tx = threadIdx.x & 31, ty = threadIdx.x >> 5;
        int x = bx * 32 + tx, y = by * 32 + ty;
        #pragma unroll
        for (int j = 0; j < 32; j += 8)
            tile[ty + j][tx] = src[(size_t)(y + j) * 1024 + x];
        __syncthreads();
        x = by * 32 + tx; y = bx * 32 + ty;
        #pragma unroll
        for (int j = 0; j < 32; j += 8)
            dst[(size_t)(y + j) * 1024 + x] = __float2half_rn(tile[tx][ty + j]);
    }
}

// ---------------------------------------------------------------------------
// Fused attention: ctx = softmax(Q K^T * scale) @ V + pe @ V
// CTA = (b, h, 64-row q-tile), 128 threads (4 warps x 16 rows), 3 CTAs/SM.
// pe converted fp32->half INLINE: LDG one tile ahead into staging regs,
// packed-half STS, fragments via ldsm4 (half the E crossbar bytes vs fp32).
// Q direct-LDG once (scale*log2e folded -> bare EX2 softmax).
// Softmax path fp16-accumulate; pe@V fp32-accumulate.
// ---------------------------------------------------------------------------
#define TB 9216                 // half tile: 64 rows * 144B
#define RSB 144
#define EOFF (4 * TB)           // E half tiles after 2x(K,V)

__global__ __launch_bounds__(128, 3)
void attn_kernel(const float* __restrict__ qf, const __half* __restrict__ kh,
                 const __half* __restrict__ vh, const float* __restrict__ pe,
                 __half* __restrict__ xout)
{
    extern __shared__ __align__(16) char smem[];
    const uint32_t sb = smem_u32(smem);

    const int b = blockIdx.x, h = blockIdx.y, q0 = blockIdx.z * 64;
    const int tid = threadIdx.x, lane = tid & 31, warp = tid >> 5;
    const int quad = lane >> 2, qt = lane & 3;
    const int rl0 = warp * 16 + quad, rh0 = rl0 + 8;

    const float*  qb  = qf + ((size_t)(b * 16 + h) * 1024 + q0) * 64;
    const __half* kb  = kh + (size_t)(b * 16 + h) * 65536;
    const __half* vb  = vh + (size_t)(b * 16 + h) * 65536;
    const float*  peb = pe + ((size_t)h * 1024 + q0) * 1024;

    // K/V chunk decomposition: 512 chunks per 64x64 half tile, 4 per thread
    int crow[4], ccol[4];
    #pragma unroll
    for (int i = 0; i < 4; ++i) {
        int c = tid + i * 128;
        crow[i] = c >> 3;
        ccol[i] = (c & 7) * 8;
    }

    auto issue_kv = [&](int kt, int buf) {
        const int k0 = kt * 64;
        const uint32_t Kb = sb + buf * 2 * TB;
        const uint32_t Vb = Kb + TB;
        #pragma unroll
        for (int i = 0; i < 4; ++i) {
            uint32_t d = crow[i] * RSB + ccol[i] * 2;
            cpa16(Kb + d, kb + (size_t)(k0 + crow[i]) * 64 + ccol[i]);
            cpa16(Vb + d, vb + (size_t)(k0 + crow[i]) * 64 + ccol[i]);
        }
    };

    // E staging: thread covers row (tid>>1), 32 floats at col (tid&1)*32
    const int er = tid >> 1;
    const int ecq = (tid & 1) * 32;
    const float* erow = peb + (size_t)er * 1024 + ecq;
    uint32_t st[16];

    auto ldg_cvt = [&](int kt) {
        const float* s = erow + kt * 64;
        #pragma unroll
        for (int i = 0; i < 8; ++i) {
            float4 f = *(const float4*)(s + i * 4);
            st[2 * i]     = h2u(f.x, f.y);
            st[2 * i + 1] = h2u(f.z, f.w);
        }
    };
    auto sts_E = [&](int buf) {
        char* d = smem + EOFF + buf * TB + er * RSB + ecq * 2;
        *(uint4*)(d)      = make_uint4(st[0],  st[1],  st[2],  st[3]);
        *(uint4*)(d + 16) = make_uint4(st[4],  st[5],  st[6],  st[7]);
        *(uint4*)(d + 32) = make_uint4(st[8],  st[9],  st[10], st[11]);
        *(uint4*)(d + 48) = make_uint4(st[12], st[13], st[14], st[15]);
    };

    issue_kv(0, 0);
    CP_COMMIT();

    // ---- Q A-fragments straight from global (scale*log2e folded in) ----
    const float c2f = 0.125f * 1.44269504088896340736f;
    const float* qrl = qb + (size_t)rl0 * 64;
    const float* qrh = qb + (size_t)rh0 * 64;
    uint32_t qa[4][4];
    #pragma unroll
    for (int kg = 0; kg < 4; ++kg) {
        const int qc = kg * 16 + 2 * qt;
        float2 a0 = *(const float2*)(qrl + qc);
        float2 a1 = *(const float2*)(qrh + qc);
        float2 a2 = *(const float2*)(qrl + qc + 8);
        float2 a3 = *(const float2*)(qrh + qc + 8);
        qa[kg][0] = h2u(a0.x * c2f, a0.y * c2f);
        qa[kg][1] = h2u(a1.x * c2f, a1.y * c2f);
        qa[kg][2] = h2u(a2.x * c2f, a2.y * c2f);
        qa[kg][3] = h2u(a3.x * c2f, a3.y * c2f);
    }
    ldg_cvt(0);   // E tile 0 into staging regs

    const uint32_t laneA = (lane & 15) * RSB + (lane >> 4) * 16;
    const uint32_t laneK = ((lane & 7) + (lane >> 4) * 8) * RSB + ((lane >> 3) & 1) * 16;
    const uint32_t laneV = ((lane & 7) + ((lane >> 3) & 1) * 8) * RSB + (lane >> 4) * 16;

    uint32_t os2[8][2] = {};       // P@V, fp16 accum
    uint32_t rsum[2] = {};         // P@1, fp16 accum
    float op[8][4] = {};           // pe@V, fp32 accum
    const uint32_t ones[2] = {0x3C003C00u, 0x3C003C00u};

    for (int kt = 0; kt < 16; ++kt) {
        const int buf = kt & 1;
        sts_E(buf);                                 // E(kt) -> smem
        if (kt < 15) { issue_kv(kt + 1, buf ^ 1); CP_COMMIT(); CP_WAIT(1); }
        else CP_WAIT(0);
        __syncthreads();
        if (kt < 15) ldg_cvt(kt + 1);               // overlaps compute below

        const uint32_t Kb = sb + buf * 2 * TB;
        const uint32_t Vb = Kb + TB;
        const uint32_t Eb = sb + EOFF + buf * TB;

        // ----- S' = (Q*c2) @ K^T (fp16 accum) -----
        uint32_t pd[8][2] = {};
        #pragma unroll
        for (int kg = 0; kg < 4; ++kg)
            #pragma unroll
            for (int ngp = 0; ngp < 4; ++ngp) {
                uint32_t kf[4];
                ldsm4(kf, Kb + ngp * (16 * RSB) + kg * 32 + laneK);
                mma16h(pd[2 * ngp], qa[kg], kf);
                mma16h(pd[2 * ngp + 1], qa[kg], kf + 2);
            }

        // ----- P = exp2(S'), in place -----
        #pragma unroll
        for (int ng = 0; ng < 8; ++ng) {
            pd[ng][0] = ex2h2(pd[ng][0]);
            pd[ng][1] = ex2h2(pd[ng][1]);
        }

        // ----- os += P @ V (fp16) ; op += E @ V (fp32) ; rsum += P @ 1 -----
        #pragma unroll
        for (int kg = 0; kg < 4; ++kg) {
            uint32_t pa[4] = {pd[2 * kg][0], pd[2 * kg][1],
                              pd[2 * kg + 1][0], pd[2 * kg + 1][1]};
            uint32_t ea[4];
            ldsm4(ea, Eb + warp * (16 * RSB) + kg * 32 + laneA);
            mma16h(rsum, pa, ones);
            #pragma unroll
            for (int ngp = 0; ngp < 4; ++ngp) {
                uint32_t vf[4];
                ldsm4t(vf, Vb + kg * (16 * RSB) + ngp * 32 + laneV);
                mma16h(os2[2 * ngp],     pa, vf);
                mma16 (op [2 * ngp],     ea, vf);
                mma16h(os2[2 * ngp + 1], pa, vf + 2);
                mma16 (op [2 * ngp + 1], ea, vf + 2);
            }
        }
        __syncthreads();
    }

    // Epilogue: ctx = os / rowsum + op -> half, layout [b, n, h*64 + c]
    const float il = 1.f / __low2float(*reinterpret_cast<__half2*>(&rsum[0]));
    const float ih = 1.f / __low2float(*reinterpret_cast<__half2*>(&rsum[1]));
    #pragma unroll
    for (int ng = 0; ng < 8; ++ng) {
        const int col = h * 64 + ng * 8 + qt * 2;
        float2 lo = __half22float2(*reinterpret_cast<__half2*>(&os2[ng][0]));
        float2 hi = __half22float2(*reinterpret_cast<__half2*>(&os2[ng][1]));
        *(uint32_t*)(xout + ((size_t)b * 1024 + q0 + rl0) * 1024 + col) =
            h2u(lo.x * il + op[ng][0], lo.y * il + op[ng][1]);
        *(uint32_t*)(xout + ((size_t)b * 1024 + q0 + rh0) * 1024 + col) =
            h2u(hi.x * ih + op[ng][2], hi.y * ih + op[ng][3]);
    }
}

// ---------------------------------------------------------------------------
// MLP GEMM (fp32 accum): out = act(A @ Wt^T + bias). 128x128 tiles,
// 3-stage cp.async pipeline, one __syncthreads per K-chunk.
// ---------------------------------------------------------------------------
#define MTB 18432               // 128 rows * 144B

__global__ __launch_bounds__(256, 2)
void mlp_tc(const __half* __restrict__ A, const __half* __restrict__ Wt,
            const float* __restrict__ bias, void* __restrict__ outp, int act)
{
    extern __shared__ __align__(16) char smem[];
    const uint32_t sb = smem_u32(smem);

    const int tid = threadIdx.x, lane = tid & 31, warp = tid >> 5;
    const int wr = warp & 3, wc = warp >> 2;
    const int quad = lane >> 2, qt = lane & 3;
    const int n0 = blockIdx.x * 128, r0 = blockIdx.y * 128;

    int crow[4], ccol[4];
    #pragma unroll
    for (int i = 0; i < 4; ++i) {
        int c = tid + i * 256;
        crow[i] = c >> 3;
        ccol[i] = (c & 7) * 8;
    }

    auto issue = [&](int kc, int buf) {
        const uint32_t Ab = sb + buf * 2 * MTB;
        const uint32_t Wb = Ab + MTB;
        #pragma unroll
        for (int i = 0; i < 4; ++i) {
            uint32_t d = crow[i] * RSB + ccol[i] * 2;
            cpa16(Ab + d, A  + (size_t)(r0 + crow[i]) * 1024 + kc * 64 + ccol[i]);
            cpa16(Wb + d, Wt + (size_t)(n0 + crow[i]) * 1024 + kc * 64 + ccol[i]);
        }
    };

    const uint32_t laneA = (lane & 15) * RSB + (lane >> 4) * 16;
    const uint32_t laneK = ((lane & 7) + (lane >> 4) * 8) * RSB + ((lane >> 3) & 1) * 16;

    float acc[2][8][4] = {};

    issue(0, 0); CP_COMMIT();
    issue(1, 1); CP_COMMIT();

    for (int kc = 0; kc < 16; ++kc) {
        const int buf = kc % 3;
        if (kc < 15) CP_WAIT(1); else CP_WAIT(0);
        __syncthreads();
        if (kc + 2 < 16) { issue(kc + 2, (kc + 2) % 3); CP_COMMIT(); }

        const uint32_t Ab = sb + buf * 2 * MTB;
        const uint32_t Wb = Ab + MTB;

        #pragma unroll
        for (int kg = 0; kg < 4; ++kg) {
            uint32_t a[2][4];
            ldsm4(a[0], Ab + (wr * 32) * RSB + kg * 32 + laneA);
            ldsm4(a[1], Ab + (wr * 32 + 16) * RSB + kg * 32 + laneA);
            #pragma unroll
            for (int ngp = 0; ngp < 4; ++ngp) {
                uint32_t wf[4];
                ldsm4(wf, Wb + (wc * 64 + ngp * 16) * RSB + kg * 32 + laneK);
                mma16(acc[0][2 * ngp],     a[0], wf);
                mma16(acc[1][2 * ngp],     a[1], wf);
                mma16(acc[0][2 * ngp + 1], a[0], wf + 2);
                mma16(acc[1][2 * ngp + 1], a[1], wf + 2);
            }
        }
    }

    #pragma unroll
    for (int t = 0; t < 2; ++t) {
        const int rr = r0 + (wr * 2 + t) * 16 + quad;
        #pragma unroll
        for (int ng = 0; ng < 8; ++ng) {
            const int col = n0 + (wc * 8 + ng) * 8 + 2 * qt;
            float2 bv = *(const float2*)(bias + col);
            float x0 = acc[t][ng][0] + bv.x, x1 = acc[t][ng][1] + bv.y;
            float x2 = acc[t][ng][2] + bv.x, x3 = acc[t][ng][3] + bv.y;
            if (act) {
                x0 = x0 / (1.f + __expf(-x0)); x1 = x1 / (1.f + __expf(-x1));
                x2 = x2 / (1.f + __expf(-x2)); x3 = x3 / (1.f + __expf(-x3));
                __half* o = (__half*)outp;
                *(uint32_t*)(o + (size_t)rr * 1024 + col)       = h2u(x0, x1);
                *(uint32_t*)(o + (size_t)(rr + 8) * 1024 + col) = h2u(x2, x3);
            } else {
                float* o = (float*)outp;
                *(float2*)(o + (size_t)rr * 1024 + col)       = make_float2(x0, x1);
                *(float2*)(o + (size_t)(rr + 8) * 1024 + col) = make_float2(x2, x3);
            }
        }
    }
}

// ---------------------------------------------------------------------------
extern "C" void kernel_launch(void* const* d_in, const int* in_sizes, int n_in,
                              void* d_out, int out_size)
{
    const float* q  = (const float*)d_in[0];
    const float* k  = (const float*)d_in[1];
    const float* v  = (const float*)d_in[2];
    const float* pe = (const float*)d_in[3];
    const float* w1 = (const float*)d_in[4];
    const float* b1 = (const float*)d_in[5];
    const float* w2 = (const float*)d_in[6];
    const float* b2 = (const float*)d_in[7];
    float* out = (float*)d_out;

    __half *kh, *vh, *xh, *hh, *w1h, *w2h;
    cudaGetSymbolAddress((void**)&kh,  g_kh);
    cudaGetSymbolAddress((void**)&vh,  g_vh);
    cudaGetSymbolAddress((void**)&xh,  g_xh);
    cudaGetSymbolAddress((void**)&hh,  g_hh);
    cudaGetSymbolAddress((void**)&w1h, g_w1h);
    cudaGetSymbolAddress((void**)&w2h, g_w2h);

    const int ATTN_SMEM = EOFF + 2 * TB;       // 2x(K,V) + 2x E-half = 55296
    const int MLP_SMEM  = 6 * MTB;             // 3-stage x (A,W) = 110592
    cudaFuncSetAttribute(attn_kernel, cudaFuncAttributeMaxDynamicSharedMemorySize, ATTN_SMEM);
    cudaFuncSetAttribute(mlp_tc,      cudaFuncAttributeMaxDynamicSharedMemorySize, MLP_SMEM);

    prep_all<<<10240, 256>>>((const float4*)k, (const float4*)v, w1, w2,
                             (uint2*)kh, (uint2*)vh, w1h, w2h);

    attn_kernel<<<dim3(4, 16, 16), 128, ATTN_SMEM>>>(q, kh, vh, pe, xh);
    mlp_tc<<<dim3(8, 32), 256, MLP_SMEM>>>(xh, w1h, b1, hh, 1);
    mlp_tc<<<dim3(8, 32), 256, MLP_SMEM>>>(hh, w2h, b2, out, 0);
}

// round 15
// speedup vs baseline: 1.2801x; 1.2801x over previous
#include <cuda_runtime.h>
#include <cuda_fp16.h>
#include <cstdint>

// Scratch (allocation-free rule: device globals)
__device__ __align__(16) __half g_kh[4194304];
__device__ __align__(16) __half g_vh[4194304];
__device__ __align__(16) __half g_xh[4194304];   // attention out (half), [B*N, D]
__device__ __align__(16) __half g_hh[4194304];   // MLP hidden (half), [B*N, D]
__device__ __align__(16) __half g_w1h[1048576];  // W1^T [out][in] half
__device__ __align__(16) __half g_w2h[1048576];  // W2^T [out][in] half

__device__ __forceinline__ uint32_t h2u(float a, float b) {
    __half2 h = __floats2half2_rn(a, b);
    return *reinterpret_cast<uint32_t*>(&h);
}
__device__ __forceinline__ uint32_t smem_u32(const void* p) {
    uint32_t a;
    asm("{ .reg .u64 t; cvta.to.shared.u64 t, %1; cvt.u32.u64 %0, t; }" : "=r"(a) : "l"(p));
    return a;
}
__device__ __forceinline__ void cpa16(uint32_t dst, const void* src) {
    asm volatile("cp.async.cg.shared.global [%0], [%1], 16;" :: "r"(dst), "l"(src));
}
#define CP_COMMIT() asm volatile("cp.async.commit_group;" ::: "memory")
#define CP_WAIT(n)  asm volatile("cp.async.wait_group %0;" :: "n"(n) : "memory")

__device__ __forceinline__ void ldsm4(uint32_t* r, uint32_t a) {
    asm volatile("ldmatrix.sync.aligned.m8n8.x4.shared.b16 {%0,%1,%2,%3}, [%4];"
        : "=r"(r[0]), "=r"(r[1]), "=r"(r[2]), "=r"(r[3]) : "r"(a));
}
__device__ __forceinline__ void ldsm4t(uint32_t* r, uint32_t a) {
    asm volatile("ldmatrix.sync.aligned.m8n8.x4.trans.shared.b16 {%0,%1,%2,%3}, [%4];"
        : "=r"(r[0]), "=r"(r[1]), "=r"(r[2]), "=r"(r[3]) : "r"(a));
}

// fp32-accumulate MMA
__device__ __forceinline__ void mma16(float* c, const uint32_t* a, const uint32_t* b) {
    asm volatile("mma.sync.aligned.m16n8k16.row.col.f32.f16.f16.f32 "
        "{%0,%1,%2,%3}, {%4,%5,%6,%7}, {%8,%9}, {%0,%1,%2,%3};"
        : "+f"(c[0]), "+f"(c[1]), "+f"(c[2]), "+f"(c[3])
        : "r"(a[0]), "r"(a[1]), "r"(a[2]), "r"(a[3]), "r"(b[0]), "r"(b[1]));
}
// fp16-accumulate MMA
__device__ __forceinline__ void mma16h(uint32_t* c, const uint32_t* a, const uint32_t* b) {
    asm volatile("mma.sync.aligned.m16n8k16.row.col.f16.f16.f16.f16 "
        "{%0,%1}, {%2,%3,%4,%5}, {%6,%7}, {%0,%1};"
        : "+r"(c[0]), "+r"(c[1])
        : "r"(a[0]), "r"(a[1]), "r"(a[2]), "r"(a[3]), "r"(b[0]), "r"(b[1]));
}
__device__ __forceinline__ uint32_t ex2h2(uint32_t x) {
    uint32_t r; asm("ex2.approx.f16x2 %0, %1;" : "=r"(r) : "r"(x)); return r;
}

// ---------------------------------------------------------------------------
// Merged prep: k/v cvt [0,8192), W1/W2 transpose+cvt [8192,10240).
// q and pe are consumed fp32 directly by the attention kernel (no prep).
// ---------------------------------------------------------------------------
__global__ __launch_bounds__(256)
void prep_all(const float4* __restrict__ k, const float4* __restrict__ v,
              const float* __restrict__ w1, const float* __restrict__ w2,
              uint2* __restrict__ ko, uint2* __restrict__ vo,
              __half* __restrict__ w1t, __half* __restrict__ w2t)
{
    __shared__ float tile[32][33];
    const int bid = blockIdx.x;
    if (bid < 8192) {
        const int sec = bid >> 12;
        const int i = (bid & 4095) * 256 + threadIdx.x;
        const float4* s = sec == 0 ? k : v;
        uint2* d = sec == 0 ? ko : vo;
        float4 t = s[i];
        d[i] = make_uint2(h2u(t.x, t.y), h2u(t.z, t.w));
    } else {
        int t = bid - 8192;
        const float* src = t < 1024 ? w1 : w2;
        __half* dst = t < 1024 ? w1t : w2t;
        t &= 1023;
        const int bx = t & 31, by = t >> 5;
        const int tx = threadIdx.x & 31, ty = threadIdx.x >> 5;
        int x = bx * 32 + tx, y = by * 32 + ty;
        #pragma unroll
        for (int j = 0; j < 32; j += 8)
            tile[ty + j][tx] = src[(size_t)(y + j) * 1024 + x];
        __syncthreads();
        x = by * 32 + tx; y = bx * 32 + ty;
        #pragma unroll
        for (int j = 0; j < 32; j += 8)
            dst[(size_t)(y + j) * 1024 + x] = __float2half_rn(tile[tx][ty + j]);
    }
}

// ---------------------------------------------------------------------------
// Fused attention: ctx = softmax(Q K^T * scale) @ V + pe @ V
// CTA = (b, h, 64-row q-tile), 128 threads (4 warps x 16 rows), 3 CTAs/SM.
// K/V half via cp.async (double-buffered + ldmatrix). pe fp32 via cp.async
// (double-buffered; E A-frags built by LDS.64 + cvt). Q direct-LDG once
// (scale*log2e folded -> bare EX2 softmax). Softmax path fp16-accumulate;
// pe@V fp32-accumulate.
// ---------------------------------------------------------------------------
#define TB 9216                 // half tile: 64 rows * 144B
#define RSB 144
#define ERS 288                 // fp32 E row stride (bytes): 64 floats + pad
#define ETB (64 * ERS)          // 18432 per buffer
#define EOFF (4 * TB)           // E buffers after 2x(K,V)

__global__ __launch_bounds__(128, 3)
void attn_kernel(const float* __restrict__ qf, const __half* __restrict__ kh,
                 const __half* __restrict__ vh, const float* __restrict__ pe,
                 __half* __restrict__ xout)
{
    extern __shared__ __align__(16) char smem[];
    const uint32_t sb = smem_u32(smem);

    const int b = blockIdx.x, h = blockIdx.y, q0 = blockIdx.z * 64;
    const int tid = threadIdx.x, lane = tid & 31, warp = tid >> 5;
    const int quad = lane >> 2, qt = lane & 3;
    const int rl0 = warp * 16 + quad, rh0 = rl0 + 8;

    const float*  qb  = qf + ((size_t)(b * 16 + h) * 1024 + q0) * 64;
    const __half* kb  = kh + (size_t)(b * 16 + h) * 65536;
    const __half* vb  = vh + (size_t)(b * 16 + h) * 65536;
    const float*  peb = pe + ((size_t)h * 1024 + q0) * 1024;

    // K/V chunk decomposition: 512 chunks per 64x64 half tile, 4 per thread
    int crow[4], ccol[4];
    #pragma unroll
    for (int i = 0; i < 4; ++i) {
        int c = tid + i * 128;
        crow[i] = c >> 3;
        ccol[i] = (c & 7) * 8;
    }
    // E fp32 chunk decomposition: 1024 chunks of 16B, 8 per thread
    int erow[8], eseg[8];
    #pragma unroll
    for (int i = 0; i < 8; ++i) {
        int c = tid + i * 128;
        erow[i] = c >> 4;
        eseg[i] = c & 15;
    }

    auto issue_tile = [&](int kt, int buf) {
        const int k0 = kt * 64;
        const uint32_t Kb = sb + buf * 2 * TB;
        const uint32_t Vb = Kb + TB;
        const uint32_t Eb = sb + EOFF + buf * ETB;
        #pragma unroll
        for (int i = 0; i < 4; ++i) {
            uint32_t d = crow[i] * RSB + ccol[i] * 2;
            cpa16(Kb + d, kb + (size_t)(k0 + crow[i]) * 64 + ccol[i]);
            cpa16(Vb + d, vb + (size_t)(k0 + crow[i]) * 64 + ccol[i]);
        }
        #pragma unroll
        for (int i = 0; i < 8; ++i) {
            uint32_t d = erow[i] * ERS + eseg[i] * 16;
            cpa16(Eb + d, peb + (size_t)erow[i] * 1024 + k0 + eseg[i] * 4);
        }
    };

    issue_tile(0, 0);
    CP_COMMIT();

    // ---- Q A-fragments straight from global (scale*log2e folded in) ----
    const float c2f = 0.125f * 1.44269504088896340736f;
    const float* qrl = qb + (size_t)rl0 * 64;
    const float* qrh = qb + (size_t)rh0 * 64;
    uint32_t qa[4][4];
    #pragma unroll
    for (int kg = 0; kg < 4; ++kg) {
        const int qc = kg * 16 + 2 * qt;
        float2 a0 = *(const float2*)(qrl + qc);
        float2 a1 = *(const float2*)(qrh + qc);
        float2 a2 = *(const float2*)(qrl + qc + 8);
        float2 a3 = *(const float2*)(qrh + qc + 8);
        qa[kg][0] = h2u(a0.x * c2f, a0.y * c2f);
        qa[kg][1] = h2u(a1.x * c2f, a1.y * c2f);
        qa[kg][2] = h2u(a2.x * c2f, a2.y * c2f);
        qa[kg][3] = h2u(a3.x * c2f, a3.y * c2f);
    }

    const uint32_t laneK = ((lane & 7) + (lane >> 4) * 8) * RSB + ((lane >> 3) & 1) * 16;
    const uint32_t laneV = ((lane & 7) + ((lane >> 3) & 1) * 8) * RSB + (lane >> 4) * 16;

    uint32_t os2[8][2] = {};       // P@V, fp16 accum
    uint32_t rsum[2] = {};         // P@1, fp16 accum
    float op[8][4] = {};           // pe@V, fp32 accum
    const uint32_t ones[2] = {0x3C003C00u, 0x3C003C00u};

    for (int kt = 0; kt < 16; ++kt) {
        const int buf = kt & 1;
        if (kt < 15) { issue_tile(kt + 1, buf ^ 1); CP_COMMIT(); CP_WAIT(1); }
        else CP_WAIT(0);
        __syncthreads();

        const uint32_t Kb = sb + buf * 2 * TB;
        const uint32_t Vb = Kb + TB;
        const char* Ef = smem + EOFF + buf * ETB;

        // ----- S' = (Q*c2) @ K^T (fp16 accum) -----
        uint32_t pd[8][2] = {};
        #pragma unroll
        for (int kg = 0; kg < 4; ++kg)
            #pragma unroll
            for (int ngp = 0; ngp < 4; ++ngp) {
                uint32_t kf[4];
                ldsm4(kf, Kb + ngp * (16 * RSB) + kg * 32 + laneK);
                mma16h(pd[2 * ngp], qa[kg], kf);
                mma16h(pd[2 * ngp + 1], qa[kg], kf + 2);
            }

        // ----- P = exp2(S'), in place -----
        #pragma unroll
        for (int ng = 0; ng < 8; ++ng) {
            pd[ng][0] = ex2h2(pd[ng][0]);
            pd[ng][1] = ex2h2(pd[ng][1]);
        }

        // ----- os += P @ V (fp16) ; op += E @ V (fp32) ; rsum += P @ 1 -----
        #pragma unroll
        for (int kg = 0; kg < 4; ++kg) {
            uint32_t pa[4] = {pd[2 * kg][0], pd[2 * kg][1],
                              pd[2 * kg + 1][0], pd[2 * kg + 1][1]};
            // E A-frag: fp32 LDS + cvt
            const int ec = kg * 16 + 2 * qt;
            float2 eA = *(const float2*)(Ef + rl0 * ERS + ec * 4);
            float2 eB = *(const float2*)(Ef + rh0 * ERS + ec * 4);
            float2 eC = *(const float2*)(Ef + rl0 * ERS + (ec + 8) * 4);
            float2 eD = *(const float2*)(Ef + rh0 * ERS + (ec + 8) * 4);
            uint32_t ea[4] = {h2u(eA.x, eA.y), h2u(eB.x, eB.y),
                              h2u(eC.x, eC.y), h2u(eD.x, eD.y)};
            mma16h(rsum, pa, ones);
            #pragma unroll
            for (int ngp = 0; ngp < 4; ++ngp) {
                uint32_t vf[4];
                ldsm4t(vf, Vb + kg * (16 * RSB) + ngp * 32 + laneV);
                mma16h(os2[2 * ngp],     pa, vf);
                mma16 (op [2 * ngp],     ea, vf);
                mma16h(os2[2 * ngp + 1], pa, vf + 2);
                mma16 (op [2 * ngp + 1], ea, vf + 2);
            }
        }
        __syncthreads();
    }

    // Epilogue: ctx = os / rowsum + op -> half, layout [b, n, h*64 + c]
    const float il = 1.f / __low2float(*reinterpret_cast<__half2*>(&rsum[0]));
    const float ih = 1.f / __low2float(*reinterpret_cast<__half2*>(&rsum[1]));
    #pragma unroll
    for (int ng = 0; ng < 8; ++ng) {
        const int col = h * 64 + ng * 8 + qt * 2;
        float2 lo = __half22float2(*reinterpret_cast<__half2*>(&os2[ng][0]));
        float2 hi = __half22float2(*reinterpret_cast<__half2*>(&os2[ng][1]));
        *(uint32_t*)(xout + ((size_t)b * 1024 + q0 + rl0) * 1024 + col) =
            h2u(lo.x * il + op[ng][0], lo.y * il + op[ng][1]);
        *(uint32_t*)(xout + ((size_t)b * 1024 + q0 + rh0) * 1024 + col) =
            h2u(hi.x * ih + op[ng][2], hi.y * ih + op[ng][3]);
    }
}

// ---------------------------------------------------------------------------
// MLP GEMM (fp32 accum): out = act(A @ Wt^T + bias). 128x128 tiles,
// 3-stage cp.async pipeline, one __syncthreads per K-chunk.
// ---------------------------------------------------------------------------
#define MTB 18432               // 128 rows * 144B

__global__ __launch_bounds__(256, 2)
void mlp_tc(const __half* __restrict__ A, const __half* __restrict__ Wt,
            const float* __restrict__ bias, void* __restrict__ outp, int act)
{
    extern __shared__ __align__(16) char smem[];
    const uint32_t sb = smem_u32(smem);

    const int tid = threadIdx.x, lane = tid & 31, warp = tid >> 5;
    const int wr = warp & 3, wc = warp >> 2;
    const int quad = lane >> 2, qt = lane & 3;
    const int n0 = blockIdx.x * 128, r0 = blockIdx.y * 128;

    int crow[4], ccol[4];
    #pragma unroll
    for (int i = 0; i < 4; ++i) {
        int c = tid + i * 256;
        crow[i] = c >> 3;
        ccol[i] = (c & 7) * 8;
    }

    auto issue = [&](int kc, int buf) {
        const uint32_t Ab = sb + buf * 2 * MTB;
        const uint32_t Wb = Ab + MTB;
        #pragma unroll
        for (int i = 0; i < 4; ++i) {
            uint32_t d = crow[i] * RSB + ccol[i] * 2;
            cpa16(Ab + d, A  + (size_t)(r0 + crow[i]) * 1024 + kc * 64 + ccol[i]);
            cpa16(Wb + d, Wt + (size_t)(n0 + crow[i]) * 1024 + kc * 64 + ccol[i]);
        }
    };

    const uint32_t laneA = (lane & 15) * RSB + (lane >> 4) * 16;
    const uint32_t laneK = ((lane & 7) + (lane >> 4) * 8) * RSB + ((lane >> 3) & 1) * 16;

    float acc[2][8][4] = {};

    issue(0, 0); CP_COMMIT();
    issue(1, 1); CP_COMMIT();

    for (int kc = 0; kc < 16; ++kc) {
        const int buf = kc % 3;
        if (kc < 15) CP_WAIT(1); else CP_WAIT(0);
        __syncthreads();
        if (kc + 2 < 16) { issue(kc + 2, (kc + 2) % 3); CP_COMMIT(); }

        const uint32_t Ab = sb + buf * 2 * MTB;
        const uint32_t Wb = Ab + MTB;

        #pragma unroll
        for (int kg = 0; kg < 4; ++kg) {
            uint32_t a[2][4];
            ldsm4(a[0], Ab + (wr * 32) * RSB + kg * 32 + laneA);
            ldsm4(a[1], Ab + (wr * 32 + 16) * RSB + kg * 32 + laneA);
            #pragma unroll
            for (int ngp = 0; ngp < 4; ++ngp) {
                uint32_t wf[4];
                ldsm4(wf, Wb + (wc * 64 + ngp * 16) * RSB + kg * 32 + laneK);
                mma16(acc[0][2 * ngp],     a[0], wf);
                mma16(acc[1][2 * ngp],     a[1], wf);
                mma16(acc[0][2 * ngp + 1], a[0], wf + 2);
                mma16(acc[1][2 * ngp + 1], a[1], wf + 2);
            }
        }
    }

    #pragma unroll
    for (int t = 0; t < 2; ++t) {
        const int rr = r0 + (wr * 2 + t) * 16 + quad;
        #pragma unroll
        for (int ng = 0; ng < 8; ++ng) {
            const int col = n0 + (wc * 8 + ng) * 8 + 2 * qt;
            float2 bv = *(const float2*)(bias + col);
            float x0 = acc[t][ng][0] + bv.x, x1 = acc[t][ng][1] + bv.y;
            float x2 = acc[t][ng][2] + bv.x, x3 = acc[t][ng][3] + bv.y;
            if (act) {
                x0 = x0 / (1.f + __expf(-x0)); x1 = x1 / (1.f + __expf(-x1));
                x2 = x2 / (1.f + __expf(-x2)); x3 = x3 / (1.f + __expf(-x3));
                __half* o = (__half*)outp;
                *(uint32_t*)(o + (size_t)rr * 1024 + col)       = h2u(x0, x1);
                *(uint32_t*)(o + (size_t)(rr + 8) * 1024 + col) = h2u(x2, x3);
            } else {
                float* o = (float*)outp;
                *(float2*)(o + (size_t)rr * 1024 + col)       = make_float2(x0, x1);
                *(float2*)(o + (size_t)(rr + 8) * 1024 + col) = make_float2(x2, x3);
            }
        }
    }
}

// ---------------------------------------------------------------------------
extern "C" void kernel_launch(void* const* d_in, const int* in_sizes, int n_in,
                              void* d_out, int out_size)
{
    const float* q  = (const float*)d_in[0];
    const float* k  = (const float*)d_in[1];
    const float* v  = (const float*)d_in[2];
    const float* pe = (const float*)d_in[3];
    const float* w1 = (const float*)d_in[4];
    const float* b1 = (const float*)d_in[5];
    const float* w2 = (const float*)d_in[6];
    const float* b2 = (const float*)d_in[7];
    float* out = (float*)d_out;

    __half *kh, *vh, *xh, *hh, *w1h, *w2h;
    cudaGetSymbolAddress((void**)&kh,  g_kh);
    cudaGetSymbolAddress((void**)&vh,  g_vh);
    cudaGetSymbolAddress((void**)&xh,  g_xh);
    cudaGetSymbolAddress((void**)&hh,  g_hh);
    cudaGetSymbolAddress((void**)&w1h, g_w1h);
    cudaGetSymbolAddress((void**)&w2h, g_w2h);

    const int ATTN_SMEM = EOFF + 2 * ETB;      // 2x(K,V) + 2x E-fp32 = 73728
    const int MLP_SMEM  = 6 * MTB;             // 3-stage x (A,W) = 110592
    cudaFuncSetAttribute(attn_kernel, cudaFuncAttributeMaxDynamicSharedMemorySize, ATTN_SMEM);
    cudaFuncSetAttribute(mlp_tc,      cudaFuncAttributeMaxDynamicSharedMemorySize, MLP_SMEM);

    prep_all<<<10240, 256>>>((const float4*)k, (const float4*)v, w1, w2,
                             (uint2*)kh, (uint2*)vh, w1h, w2h);

    attn_kernel<<<dim3(4, 16, 16), 128, ATTN_SMEM>>>(q, kh, vh, pe, xh);
    mlp_tc<<<dim3(8, 32), 256, MLP_SMEM>>>(xh, w1h, b1, hh, 1);
    mlp_tc<<<dim3(8, 32), 256, MLP_SMEM>>>(hh, w2h, b2, out, 0);
}